// round 5
// baseline (speedup 1.0000x reference)
#include <cuda_runtime.h>
#include <cstdint>
#include <math.h>

#define T_TOK 4096
#define H_DIM 2048
#define I_DIM 1408
#define E_NUM 8
#define NPAIR 8192
#define NROWS 9216            // NPAIR + E_NUM*128 padding

// ---------------- scratch (device globals) ----------------
__device__ int   g_off[E_NUM + 1];        // padded per-expert offsets (mult of 128)
__device__ int   g_rows_token[NROWS];
__device__ int   g_pos[NPAIR];            // pair -> padded slot
__device__ float g_Ax[(size_t)NROWS * H_DIM];                // AFRAG activations
__device__ float g_inter[(size_t)NROWS * I_DIM];             // AFRAG swiglu out
__device__ float g_out2[(size_t)NROWS * H_DIM];              // row-major down out
__device__ float g_w1[(size_t)E_NUM * 2 * I_DIM * H_DIM];    // BFRAG gate/up interleaved
__device__ float g_dw[(size_t)E_NUM * H_DIM * I_DIM];        // BFRAG down

// ---------------- helpers ----------------
__device__ __forceinline__ uint32_t smem_u32(const void* p) {
    uint32_t a;
    asm("{ .reg .u64 t; cvta.to.shared.u64 t, %1; cvt.u32.u64 %0, t; }" : "=r"(a) : "l"(p));
    return a;
}
__device__ __forceinline__ float rna(float x) {
    uint32_t r;
    asm("cvt.rna.tf32.f32 %0, %1;" : "=r"(r) : "f"(x));
    return __uint_as_float(r);
}
__device__ __forceinline__ void cpa16(uint32_t dst, const float* src) {
    asm volatile("cp.async.cg.shared.global [%0], [%1], 16;" :: "r"(dst), "l"(src));
}
#define CPA_COMMIT() asm volatile("cp.async.commit_group;" ::: "memory")
#define CPA_WAIT1()  asm volatile("cp.async.wait_group 1;" ::: "memory")
#define CPA_WAIT0()  asm volatile("cp.async.wait_group 0;" ::: "memory")
#define FU(x) __float_as_uint(x)

__device__ __forceinline__ void mma_tf32(float c[4], const uint32_t a[4], uint32_t b0, uint32_t b1) {
    asm volatile("mma.sync.aligned.m16n8k8.row.col.f32.tf32.tf32.f32 "
                 "{%0,%1,%2,%3}, {%4,%5,%6,%7}, {%8,%9}, {%0,%1,%2,%3};"
                 : "+f"(c[0]), "+f"(c[1]), "+f"(c[2]), "+f"(c[3])
                 : "r"(a[0]), "r"(a[1]), "r"(a[2]), "r"(a[3]), "r"(b0), "r"(b1));
}

#define STAGE_B 49152            // A 16KB + B 32KB
#define NSTAGE 3
#define SMEM_BYTES (NSTAGE * STAGE_B)   // 147456
#define B_OFF_F 4096             // float offset of B region in stage

// ---------------- routing (padded offsets) ----------------
__global__ void route_kernel(const int* __restrict__ idx) {
    __shared__ int cnt[E_NUM];
    __shared__ int off[E_NUM + 1];
    int tid = threadIdx.x;
    for (int p = tid; p < NROWS; p += 256) g_rows_token[p] = 0;
    if (tid < E_NUM) cnt[tid] = 0;
    __syncthreads();
    for (int p = tid; p < NPAIR; p += 256) atomicAdd(&cnt[idx[p]], 1);
    __syncthreads();
    if (tid == 0) {
        int s = 0;
        for (int e = 0; e < E_NUM; e++) { off[e] = s; s += ((cnt[e] + 127) >> 7) << 7; }
        off[E_NUM] = s;
        for (int e = 0; e <= E_NUM; e++) g_off[e] = off[e];
    }
    __syncthreads();
    if (tid < E_NUM) cnt[tid] = off[tid];
    __syncthreads();
    for (int p = tid; p < NPAIR; p += 256) {
        int e = idx[p];
        int pos = atomicAdd(&cnt[e], 1);
        g_rows_token[pos] = p >> 1;
        g_pos[p] = pos;
    }
}

// ---------------- gather -> AFRAG (+rna) ----------------
__global__ void gather_kernel(const float* __restrict__ x) {
    int mb = blockIdx.x;
    int tid = threadIdx.x, lane = tid & 31, ws = tid >> 5;
    int lr = lane >> 2, lc = lane & 3;
    const float* r0 = x + (size_t)g_rows_token[mb * 16 + lr] * H_DIM;
    const float* r1 = x + (size_t)g_rows_token[mb * 16 + 8 + lr] * H_DIM;
    float4* dst = (float4*)g_Ax + (size_t)mb * 256 * 32 + lane;
    #pragma unroll 4
    for (int it = 0; it < 32; it++) {
        int k8 = ws + 8 * it;
        int k = k8 * 8;
        float4 v;
        v.x = rna(r0[k + lc]);
        v.y = rna(r1[k + lc]);
        v.z = rna(r0[k + 4 + lc]);
        v.w = rna(r1[k + 4 + lc]);
        dst[(size_t)k8 * 32] = v;
    }
}

// ---------------- weights -> BFRAG (+rna) ----------------
__global__ void permw1_kernel(const float* __restrict__ gate_w, const float* __restrict__ up_w) {
    int bid = blockIdx.x;
    int e = bid / 352, nb = bid % 352;
    int tid = threadIdx.x, lane = tid & 31, ws = tid >> 5;
    int lr = lane >> 2, lc = lane & 3;
    int n = nb * 8 + lr, i = n >> 1;
    const float* src = ((n & 1) ? up_w : gate_w) + ((size_t)e * I_DIM + i) * H_DIM;
    float4* dst = (float4*)g_w1 + (size_t)bid * 128 * 32 + lane;
    #pragma unroll 4
    for (int it = 0; it < 16; it++) {
        int k16 = ws + 8 * it;
        int k = k16 * 16;
        float4 v;
        v.x = rna(src[k + lc]);
        v.y = rna(src[k + 4 + lc]);
        v.z = rna(src[k + 8 + lc]);
        v.w = rna(src[k + 12 + lc]);
        dst[(size_t)k16 * 32] = v;
    }
}

__global__ void permdw_kernel(const float* __restrict__ down_w) {
    int bid = blockIdx.x;
    int e = bid >> 8, nb = bid & 255;
    int tid = threadIdx.x, lane = tid & 31, ws = tid >> 5;
    int lr = lane >> 2, lc = lane & 3;
    int h = nb * 8 + lr;
    const float* src = down_w + ((size_t)e * H_DIM + h) * I_DIM;
    float4* dst = (float4*)g_dw + (size_t)bid * 88 * 32 + lane;
    #pragma unroll
    for (int it = 0; it < 11; it++) {
        int k16 = ws + 8 * it;
        int k = k16 * 16;
        float4 v;
        v.x = rna(src[k + lc]);
        v.y = rna(src[k + 4 + lc]);
        v.z = rna(src[k + 8 + lc]);
        v.w = rna(src[k + 12 + lc]);
        dst[(size_t)k16 * 32] = v;
    }
}

// ---------------- GEMM core: warp tile 64x64, chunk K=32 ----------------
__device__ __forceinline__ void tile_compute(const float* stg, int mtb, int ntb,
                                             int lane, float acc[4][8][4]) {
    const float* stgB = stg + B_OFF_F;
    #pragma unroll
    for (int kp = 0; kp < 2; kp++) {          // two k16 groups
        float4 bfr[8];
        #pragma unroll
        for (int nt = 0; nt < 8; nt++)
            bfr[nt] = *(const float4*)(stgB + ((ntb + nt) * 2 + kp) * 128 + lane * 4);
        #pragma unroll
        for (int kh = 0; kh < 2; kh++) {      // k8 within k16
            #pragma unroll
            for (int mt = 0; mt < 4; mt++) {
                float4 af = *(const float4*)(stg + ((mtb + mt) * 4 + kp * 2 + kh) * 128 + lane * 4);
                uint32_t a[4] = {FU(af.x), FU(af.y), FU(af.z), FU(af.w)};
                #pragma unroll
                for (int nt = 0; nt < 8; nt++) {
                    if (kh == 0) mma_tf32(acc[mt][nt], a, FU(bfr[nt].x), FU(bfr[nt].y));
                    else         mma_tf32(acc[mt][nt], a, FU(bfr[nt].z), FU(bfr[nt].w));
                }
            }
        }
    }
}

// ---------------- GEMM1: Ax @ [gate;up]^T, SwiGLU -> AFRAG ----------------
#define NC1 64

__global__ void __launch_bounds__(256, 1)
gemm1_kernel() {
    const int e = blockIdx.z;
    const int base = g_off[e];
    const int Npad = g_off[e + 1] - base;
    const int m0 = blockIdx.y * 128;
    if (m0 >= Npad) return;
    const int bx = blockIdx.x;                 // 128 i = 256 n per block
    const int mb0 = (base + m0) >> 4;
    const int nb0 = bx * 32;

    extern __shared__ char smem[];
    const uint32_t sb = smem_u32(smem);
    const int tid = threadIdx.x, lane = tid & 31, wid = tid >> 5;
    const int mtb = (wid & 1) * 4, ntb = (wid >> 1) * 8;

    // cp.async: 4 A-blocks + 8 B-blocks per thread per stage
    uint32_t a_off[4], b_off[8];
    const float* a_src[4];
    const float* b_src[8];
    #pragma unroll
    for (int j = 0; j < 4; j++) {
        int idx = tid + j * 256;
        int fb = idx >> 5, ln = idx & 31;
        int mbl = fb >> 2, k8l = fb & 3;
        a_off[j] = (mbl * 4 + k8l) * 512 + ln * 16;
        a_src[j] = g_Ax + (((size_t)(mb0 + mbl) * 256 + k8l) * 32 + ln) * 4;
    }
    #pragma unroll
    for (int j = 0; j < 8; j++) {
        int idx = tid + j * 256;
        int fb = idx >> 5, ln = idx & 31;
        int nbl = fb >> 1, k16l = fb & 1;
        b_off[j] = 16384 + (nbl * 2 + k16l) * 512 + ln * 16;
        b_src[j] = g_w1 + (((size_t)(e * 352 + nb0 + nbl) * 128 + k16l) * 32 + ln) * 4;
    }

    float acc[4][8][4];
    #pragma unroll
    for (int mt = 0; mt < 4; mt++)
        #pragma unroll
        for (int nt = 0; nt < 8; nt++)
            #pragma unroll
            for (int q = 0; q < 4; q++) acc[mt][nt][q] = 0.f;

    #pragma unroll
    for (int s = 0; s < 2; s++) {
        uint32_t st = sb + s * STAGE_B;
        #pragma unroll
        for (int j = 0; j < 4; j++) cpa16(st + a_off[j], a_src[j] + s * 512);
        #pragma unroll
        for (int j = 0; j < 8; j++) cpa16(st + b_off[j], b_src[j] + s * 256);
        CPA_COMMIT();
    }
    #pragma unroll
    for (int j = 0; j < 4; j++) a_src[j] += 1024;
    #pragma unroll
    for (int j = 0; j < 8; j++) b_src[j] += 512;

    for (int c = 0; c < NC1; c++) {
        if (c >= NC1 - 1) CPA_WAIT0(); else CPA_WAIT1();
        __syncthreads();
        if (c + 2 < NC1) {
            uint32_t st = sb + ((c + 2) % NSTAGE) * STAGE_B;
            #pragma unroll
            for (int j = 0; j < 4; j++) { cpa16(st + a_off[j], a_src[j]); a_src[j] += 512; }
            #pragma unroll
            for (int j = 0; j < 8; j++) { cpa16(st + b_off[j], b_src[j]); b_src[j] += 256; }
            CPA_COMMIT();
        }
        tile_compute((const float*)(smem + (c % NSTAGE) * STAGE_B), mtb, ntb, lane, acc);
    }

    // epilogue: silu(gate)*up -> g_inter AFRAG
    const int i_k8base = bx * 16 + (wid >> 1) * 4;
    const int mbGbase = mb0 + (wid & 1) * 4;
    #pragma unroll
    for (int mt = 0; mt < 4; mt++) {
        #pragma unroll
        for (int b = 0; b < 4; b++) {
            float g, u;
            float4 v;
            g = acc[mt][2 * b][0];     u = acc[mt][2 * b][1];
            v.x = rna(g / (1.f + __expf(-g)) * u);
            g = acc[mt][2 * b][2];     u = acc[mt][2 * b][3];
            v.y = rna(g / (1.f + __expf(-g)) * u);
            g = acc[mt][2 * b + 1][0]; u = acc[mt][2 * b + 1][1];
            v.z = rna(g / (1.f + __expf(-g)) * u);
            g = acc[mt][2 * b + 1][2]; u = acc[mt][2 * b + 1][3];
            v.w = rna(g / (1.f + __expf(-g)) * u);
            *((float4*)g_inter + ((size_t)(mbGbase + mt) * 176 + i_k8base + b) * 32 + lane) = v;
        }
    }
}

// ---------------- GEMM2: inter @ down^T -> row-major g_out2 ----------------
#define NC2 44

__global__ void __launch_bounds__(256, 1)
gemm2_kernel() {
    const int e = blockIdx.z;
    const int base = g_off[e];
    const int Npad = g_off[e + 1] - base;
    const int m0 = blockIdx.y * 128;
    if (m0 >= Npad) return;
    const int bx = blockIdx.x;                 // 256 h per block
    const int mb0 = (base + m0) >> 4;
    const int nb0 = bx * 32;
    const int h0 = bx * 256;

    extern __shared__ char smem[];
    const uint32_t sb = smem_u32(smem);
    const int tid = threadIdx.x, lane = tid & 31, wid = tid >> 5;
    const int mtb = (wid & 1) * 4, ntb = (wid >> 1) * 8;

    uint32_t a_off[4], b_off[8];
    const float* a_src[4];
    const float* b_src[8];
    #pragma unroll
    for (int j = 0; j < 4; j++) {
        int idx = tid + j * 256;
        int fb = idx >> 5, ln = idx & 31;
        int mbl = fb >> 2, k8l = fb & 3;
        a_off[j] = (mbl * 4 + k8l) * 512 + ln * 16;
        a_src[j] = g_inter + (((size_t)(mb0 + mbl) * 176 + k8l) * 32 + ln) * 4;
    }
    #pragma unroll
    for (int j = 0; j < 8; j++) {
        int idx = tid + j * 256;
        int fb = idx >> 5, ln = idx & 31;
        int nbl = fb >> 1, k16l = fb & 1;
        b_off[j] = 16384 + (nbl * 2 + k16l) * 512 + ln * 16;
        b_src[j] = g_dw + (((size_t)(e * 256 + nb0 + nbl) * 88 + k16l) * 32 + ln) * 4;
    }

    float acc[4][8][4];
    #pragma unroll
    for (int mt = 0; mt < 4; mt++)
        #pragma unroll
        for (int nt = 0; nt < 8; nt++)
            #pragma unroll
            for (int q = 0; q < 4; q++) acc[mt][nt][q] = 0.f;

    #pragma unroll
    for (int s = 0; s < 2; s++) {
        uint32_t st = sb + s * STAGE_B;
        #pragma unroll
        for (int j = 0; j < 4; j++) cpa16(st + a_off[j], a_src[j] + s * 512);
        #pragma unroll
        for (int j = 0; j < 8; j++) cpa16(st + b_off[j], b_src[j] + s * 256);
        CPA_COMMIT();
    }
    #pragma unroll
    for (int j = 0; j < 4; j++) a_src[j] += 1024;
    #pragma unroll
    for (int j = 0; j < 8; j++) b_src[j] += 512;

    for (int c = 0; c < NC2; c++) {
        if (c >= NC2 - 1) CPA_WAIT0(); else CPA_WAIT1();
        __syncthreads();
        if (c + 2 < NC2) {
            uint32_t st = sb + ((c + 2) % NSTAGE) * STAGE_B;
            #pragma unroll
            for (int j = 0; j < 4; j++) { cpa16(st + a_off[j], a_src[j]); a_src[j] += 512; }
            #pragma unroll
            for (int j = 0; j < 8; j++) { cpa16(st + b_off[j], b_src[j]); b_src[j] += 256; }
            CPA_COMMIT();
        }
        tile_compute((const float*)(smem + (c % NSTAGE) * STAGE_B), mtb, ntb, lane, acc);
    }

    // epilogue: row-major float2 stores
    const int lr = lane >> 2, lc = lane & 3;
    const int rbase = base + m0 + (wid & 1) * 64 + lr;
    #pragma unroll
    for (int mt = 0; mt < 4; mt++) {
        int r = rbase + mt * 16;
        #pragma unroll
        for (int nt = 0; nt < 8; nt++) {
            int h = h0 + (wid >> 1) * 64 + nt * 8 + 2 * lc;
            *(float2*)(g_out2 + (size_t)r * H_DIM + h) =
                make_float2(acc[mt][nt][0], acc[mt][nt][1]);
            *(float2*)(g_out2 + (size_t)(r + 8) * H_DIM + h) =
                make_float2(acc[mt][nt][2], acc[mt][nt][3]);
        }
    }
}

// ---------------- combine ----------------
__global__ void combine_kernel(const float* __restrict__ w, float* __restrict__ out) {
    int t = blockIdx.x;
    float w0 = w[2 * t], w1 = w[2 * t + 1];
    const float4* a = (const float4*)(g_out2 + (size_t)g_pos[2 * t] * H_DIM);
    const float4* b = (const float4*)(g_out2 + (size_t)g_pos[2 * t + 1] * H_DIM);
    float4* o = (float4*)(out + (size_t)t * H_DIM);
    for (int j = threadIdx.x; j < H_DIM / 4; j += 256) {
        float4 va = a[j], vb = b[j], r;
        r.x = w0 * va.x + w1 * vb.x;
        r.y = w0 * va.y + w1 * vb.y;
        r.z = w0 * va.z + w1 * vb.z;
        r.w = w0 * va.w + w1 * vb.w;
        o[j] = r;
    }
}

// ---------------- launch ----------------
extern "C" void kernel_launch(void* const* d_in, const int* in_sizes, int n_in,
                              void* d_out, int out_size) {
    const float* hidden = (const float*)d_in[0];
    const int*   topk_i = (const int*)d_in[1];
    const float* topk_w = (const float*)d_in[2];
    const float* gate_w = (const float*)d_in[3];
    const float* up_w   = (const float*)d_in[4];
    const float* down_w = (const float*)d_in[5];
    float* out = (float*)d_out;

    cudaFuncSetAttribute(gemm1_kernel, cudaFuncAttributeMaxDynamicSharedMemorySize, SMEM_BYTES);
    cudaFuncSetAttribute(gemm2_kernel, cudaFuncAttributeMaxDynamicSharedMemorySize, SMEM_BYTES);

    route_kernel<<<1, 256>>>(topk_i);
    gather_kernel<<<NROWS / 16, 256>>>(hidden);
    permw1_kernel<<<E_NUM * 352, 256>>>(gate_w, up_w);
    permdw_kernel<<<E_NUM * 256, 256>>>(down_w);

    dim3 g1(I_DIM / 128, 72, E_NUM);   // (11, 72, 8) — y covers max padded rows
    gemm1_kernel<<<g1, 256, SMEM_BYTES>>>();

    dim3 g2(H_DIM / 256, 72, E_NUM);   // (8, 72, 8)
    gemm2_kernel<<<g2, 256, SMEM_BYTES>>>();

    combine_kernel<<<T_TOK, 256>>>(topk_w, out);
}

// round 8
// speedup vs baseline: 1.0687x; 1.0687x over previous
#include <cuda_runtime.h>
#include <cstdint>
#include <math.h>

#define T_TOK 4096
#define H_DIM 2048
#define I_DIM 1408
#define E_NUM 8
#define NPAIR 8192
#define NROWS 9216            // NPAIR + E_NUM*128 padding

// ---------------- scratch (device globals) ----------------
__device__ int   g_off[E_NUM + 1];        // padded per-expert offsets (mult of 128)
__device__ int   g_rows_token[NROWS];
__device__ int   g_pos[NPAIR];            // pair -> padded slot
__device__ float g_Ax[(size_t)NROWS * H_DIM];                // AFRAG activations
__device__ float g_inter[(size_t)NROWS * I_DIM];             // AFRAG swiglu out
__device__ float g_out2[(size_t)NROWS * H_DIM];              // row-major down out
__device__ float g_w1[(size_t)E_NUM * 2 * I_DIM * H_DIM];    // BFRAG gate/up interleaved
__device__ float g_dw[(size_t)E_NUM * H_DIM * I_DIM];        // BFRAG down

// ---------------- helpers ----------------
__device__ __forceinline__ uint32_t smem_u32(const void* p) {
    uint32_t a;
    asm("{ .reg .u64 t; cvta.to.shared.u64 t, %1; cvt.u32.u64 %0, t; }" : "=r"(a) : "l"(p));
    return a;
}
__device__ __forceinline__ float rna(float x) {
    uint32_t r;
    asm("cvt.rna.tf32.f32 %0, %1;" : "=r"(r) : "f"(x));
    return __uint_as_float(r);
}
__device__ __forceinline__ void cpa16(uint32_t dst, const float* src) {
    asm volatile("cp.async.cg.shared.global [%0], [%1], 16;" :: "r"(dst), "l"(src));
}
#define CPA_COMMIT() asm volatile("cp.async.commit_group;" ::: "memory")
#define CPA_WAIT1()  asm volatile("cp.async.wait_group 1;" ::: "memory")
#define CPA_WAIT0()  asm volatile("cp.async.wait_group 0;" ::: "memory")
#define FU(x) __float_as_uint(x)

__device__ __forceinline__ void mma_tf32(float c[4], const uint32_t a[4], uint32_t b0, uint32_t b1) {
    asm volatile("mma.sync.aligned.m16n8k8.row.col.f32.tf32.tf32.f32 "
                 "{%0,%1,%2,%3}, {%4,%5,%6,%7}, {%8,%9}, {%0,%1,%2,%3};"
                 : "+f"(c[0]), "+f"(c[1]), "+f"(c[2]), "+f"(c[3])
                 : "r"(a[0]), "r"(a[1]), "r"(a[2]), "r"(a[3]), "r"(b0), "r"(b1));
}

#define STAGE_B 32768
#define NSTAGE 3
#define SMEM_BYTES (NSTAGE * STAGE_B)   // 98304

// ---------------- routing (padded offsets) ----------------
__global__ void route_kernel(const int* __restrict__ idx) {
    __shared__ int cnt[E_NUM];
    __shared__ int off[E_NUM + 1];
    int tid = threadIdx.x;
    for (int p = tid; p < NROWS; p += 256) g_rows_token[p] = 0;
    if (tid < E_NUM) cnt[tid] = 0;
    __syncthreads();
    for (int p = tid; p < NPAIR; p += 256) atomicAdd(&cnt[idx[p]], 1);
    __syncthreads();
    if (tid == 0) {
        int s = 0;
        for (int e = 0; e < E_NUM; e++) { off[e] = s; s += ((cnt[e] + 127) >> 7) << 7; }
        off[E_NUM] = s;
        for (int e = 0; e <= E_NUM; e++) g_off[e] = off[e];
    }
    __syncthreads();
    if (tid < E_NUM) cnt[tid] = off[tid];
    __syncthreads();
    for (int p = tid; p < NPAIR; p += 256) {
        int e = idx[p];
        int pos = atomicAdd(&cnt[e], 1);
        g_rows_token[pos] = p >> 1;
        g_pos[p] = pos;
    }
}

// ---------------- gather -> AFRAG (+rna) ----------------
__global__ void gather_kernel(const float* __restrict__ x) {
    int mb = blockIdx.x;
    int tid = threadIdx.x, lane = tid & 31, ws = tid >> 5;
    int lr = lane >> 2, lc = lane & 3;
    const float* r0 = x + (size_t)g_rows_token[mb * 16 + lr] * H_DIM;
    const float* r1 = x + (size_t)g_rows_token[mb * 16 + 8 + lr] * H_DIM;
    float4* dst = (float4*)g_Ax + (size_t)mb * 256 * 32 + lane;
    #pragma unroll 4
    for (int it = 0; it < 32; it++) {
        int k8 = ws + 8 * it;
        int k = k8 * 8;
        float4 v;
        v.x = rna(r0[k + lc]);
        v.y = rna(r1[k + lc]);
        v.z = rna(r0[k + 4 + lc]);
        v.w = rna(r1[k + 4 + lc]);
        dst[(size_t)k8 * 32] = v;
    }
}

// ---------------- weights -> BFRAG (+rna) ----------------
__global__ void permw1_kernel(const float* __restrict__ gate_w, const float* __restrict__ up_w) {
    int bid = blockIdx.x;
    int e = bid / 352, nb = bid % 352;
    int tid = threadIdx.x, lane = tid & 31, ws = tid >> 5;
    int lr = lane >> 2, lc = lane & 3;
    int n = nb * 8 + lr, i = n >> 1;
    const float* src = ((n & 1) ? up_w : gate_w) + ((size_t)e * I_DIM + i) * H_DIM;
    float4* dst = (float4*)g_w1 + (size_t)bid * 128 * 32 + lane;
    #pragma unroll 4
    for (int it = 0; it < 16; it++) {
        int k16 = ws + 8 * it;
        int k = k16 * 16;
        float4 v;
        v.x = rna(src[k + lc]);
        v.y = rna(src[k + 4 + lc]);
        v.z = rna(src[k + 8 + lc]);
        v.w = rna(src[k + 12 + lc]);
        dst[(size_t)k16 * 32] = v;
    }
}

__global__ void permdw_kernel(const float* __restrict__ down_w) {
    int bid = blockIdx.x;
    int e = bid >> 8, nb = bid & 255;
    int tid = threadIdx.x, lane = tid & 31, ws = tid >> 5;
    int lr = lane >> 2, lc = lane & 3;
    int h = nb * 8 + lr;
    const float* src = down_w + ((size_t)e * H_DIM + h) * I_DIM;
    float4* dst = (float4*)g_dw + (size_t)bid * 88 * 32 + lane;
    #pragma unroll
    for (int it = 0; it < 11; it++) {
        int k16 = ws + 8 * it;
        int k = k16 * 16;
        float4 v;
        v.x = rna(src[k + lc]);
        v.y = rna(src[k + 4 + lc]);
        v.z = rna(src[k + 8 + lc]);
        v.w = rna(src[k + 12 + lc]);
        dst[(size_t)k16 * 32] = v;
    }
}

// ---------------- GEMM core: warp tile 64x32, chunk K=32 ----------------
__device__ __forceinline__ void tile_compute(const float* stg, int mtb, int ntb,
                                             int lane, float acc[4][4][4]) {
    const float* stgB = stg + 4096;
    float4 bfr[4];
    #pragma unroll
    for (int kk = 0; kk < 4; kk++) {
        if ((kk & 1) == 0) {
            #pragma unroll
            for (int nt = 0; nt < 4; nt++)
                bfr[nt] = *(const float4*)(stgB + ((ntb + nt) * 2 + (kk >> 1)) * 128 + lane * 4);
        }
        #pragma unroll
        for (int mt = 0; mt < 4; mt++) {
            float4 af = *(const float4*)(stg + ((mtb + mt) * 4 + kk) * 128 + lane * 4);
            uint32_t a[4] = {FU(af.x), FU(af.y), FU(af.z), FU(af.w)};
            #pragma unroll
            for (int nt = 0; nt < 4; nt++) {
                if ((kk & 1) == 0) mma_tf32(acc[mt][nt], a, FU(bfr[nt].x), FU(bfr[nt].y));
                else               mma_tf32(acc[mt][nt], a, FU(bfr[nt].z), FU(bfr[nt].w));
            }
        }
    }
}

// ---------------- GEMM1: Ax @ [gate;up]^T (interleaved), SwiGLU -> AFRAG ----
#define NC1 64

__global__ void __launch_bounds__(256, 2)
gemm1_kernel() {
    const int e = blockIdx.z;
    const int base = g_off[e];
    const int Npad = g_off[e + 1] - base;
    const int m0 = blockIdx.y * 128;
    if (m0 >= Npad) return;
    const int bx = blockIdx.x;                 // i-block: 64 i = 128 n = 16 nb
    const int mb0 = (base + m0) >> 4;
    const int nb0 = bx * 16;

    extern __shared__ char smem[];
    const uint32_t sb = smem_u32(smem);
    const int tid = threadIdx.x, lane = tid & 31, wid = tid >> 5;
    const int mtb = (wid & 1) * 4, ntb = (wid >> 1) * 4;

    uint32_t a_off[4], b_off[4];
    const float* a_src[4];
    const float* b_src[4];
    #pragma unroll
    for (int j = 0; j < 4; j++) {
        int idx = tid + j * 256;
        int fb = idx >> 5, ln = idx & 31;
        int mbl = fb >> 2, k8l = fb & 3;
        a_off[j] = (mbl * 4 + k8l) * 512 + ln * 16;
        a_src[j] = g_Ax + (((size_t)(mb0 + mbl) * 256 + k8l) * 32 + ln) * 4;
        int nbl = fb >> 1, k16l = fb & 1;
        b_off[j] = 16384 + (nbl * 2 + k16l) * 512 + ln * 16;
        b_src[j] = g_w1 + (((size_t)(e * 352 + nb0 + nbl) * 128 + k16l) * 32 + ln) * 4;
    }

    float acc[4][4][4];
    #pragma unroll
    for (int mt = 0; mt < 4; mt++)
        #pragma unroll
        for (int nt = 0; nt < 4; nt++)
            #pragma unroll
            for (int q = 0; q < 4; q++) acc[mt][nt][q] = 0.f;

    #pragma unroll
    for (int s = 0; s < 2; s++) {
        uint32_t st = sb + s * STAGE_B;
        #pragma unroll
        for (int j = 0; j < 4; j++) {
            cpa16(st + a_off[j], a_src[j] + s * 512);
            cpa16(st + b_off[j], b_src[j] + s * 256);
        }
        CPA_COMMIT();
    }
    #pragma unroll
    for (int j = 0; j < 4; j++) { a_src[j] += 1024; b_src[j] += 512; }

    for (int c = 0; c < NC1; c++) {
        if (c >= NC1 - 1) CPA_WAIT0(); else CPA_WAIT1();
        __syncthreads();
        if (c + 2 < NC1) {
            uint32_t st = sb + ((c + 2) % NSTAGE) * STAGE_B;
            #pragma unroll
            for (int j = 0; j < 4; j++) {
                cpa16(st + a_off[j], a_src[j]);
                cpa16(st + b_off[j], b_src[j]);
                a_src[j] += 512; b_src[j] += 256;
            }
            CPA_COMMIT();
        }
        tile_compute((const float*)(smem + (c % NSTAGE) * STAGE_B), mtb, ntb, lane, acc);
    }

    // epilogue: silu(gate)*up -> g_inter AFRAG (coalesced STG.128)
    const int i_k8base = bx * 8 + (wid >> 1) * 2;
    const int mbGbase = mb0 + (wid & 1) * 4;
    #pragma unroll
    for (int mt = 0; mt < 4; mt++) {
        #pragma unroll
        for (int b = 0; b < 2; b++) {
            float g, u;
            float4 v;
            g = acc[mt][2 * b][0];     u = acc[mt][2 * b][1];
            v.x = rna(g / (1.f + __expf(-g)) * u);
            g = acc[mt][2 * b][2];     u = acc[mt][2 * b][3];
            v.y = rna(g / (1.f + __expf(-g)) * u);
            g = acc[mt][2 * b + 1][0]; u = acc[mt][2 * b + 1][1];
            v.z = rna(g / (1.f + __expf(-g)) * u);
            g = acc[mt][2 * b + 1][2]; u = acc[mt][2 * b + 1][3];
            v.w = rna(g / (1.f + __expf(-g)) * u);
            *((float4*)g_inter + ((size_t)(mbGbase + mt) * 176 + i_k8base + b) * 32 + lane) = v;
        }
    }
}

// ---------------- GEMM2: inter @ down^T -> row-major g_out2 ----------------
#define NC2 44

__global__ void __launch_bounds__(256, 2)
gemm2_kernel() {
    const int e = blockIdx.z;
    const int base = g_off[e];
    const int Npad = g_off[e + 1] - base;
    const int m0 = blockIdx.y * 128;
    if (m0 >= Npad) return;
    const int bx = blockIdx.x;                 // h-block of 128
    const int mb0 = (base + m0) >> 4;
    const int nb0 = bx * 16;
    const int h0 = bx * 128;

    extern __shared__ char smem[];
    const uint32_t sb = smem_u32(smem);
    const int tid = threadIdx.x, lane = tid & 31, wid = tid >> 5;
    const int mtb = (wid & 1) * 4, ntb = (wid >> 1) * 4;

    uint32_t a_off[4], b_off[4];
    const float* a_src[4];
    const float* b_src[4];
    #pragma unroll
    for (int j = 0; j < 4; j++) {
        int idx = tid + j * 256;
        int fb = idx >> 5, ln = idx & 31;
        int mbl = fb >> 2, k8l = fb & 3;
        a_off[j] = (mbl * 4 + k8l) * 512 + ln * 16;
        a_src[j] = g_inter + (((size_t)(mb0 + mbl) * 176 + k8l) * 32 + ln) * 4;
        int nbl = fb >> 1, k16l = fb & 1;
        b_off[j] = 16384 + (nbl * 2 + k16l) * 512 + ln * 16;
        b_src[j] = g_dw + (((size_t)(e * 256 + nb0 + nbl) * 88 + k16l) * 32 + ln) * 4;
    }

    float acc[4][4][4];
    #pragma unroll
    for (int mt = 0; mt < 4; mt++)
        #pragma unroll
        for (int nt = 0; nt < 4; nt++)
            #pragma unroll
            for (int q = 0; q < 4; q++) acc[mt][nt][q] = 0.f;

    #pragma unroll
    for (int s = 0; s < 2; s++) {
        uint32_t st = sb + s * STAGE_B;
        #pragma unroll
        for (int j = 0; j < 4; j++) {
            cpa16(st + a_off[j], a_src[j] + s * 512);
            cpa16(st + b_off[j], b_src[j] + s * 256);
        }
        CPA_COMMIT();
    }
    #pragma unroll
    for (int j = 0; j < 4; j++) { a_src[j] += 1024; b_src[j] += 512; }

    for (int c = 0; c < NC2; c++) {
        if (c >= NC2 - 1) CPA_WAIT0(); else CPA_WAIT1();
        __syncthreads();
        if (c + 2 < NC2) {
            uint32_t st = sb + ((c + 2) % NSTAGE) * STAGE_B;
            #pragma unroll
            for (int j = 0; j < 4; j++) {
                cpa16(st + a_off[j], a_src[j]);
                cpa16(st + b_off[j], b_src[j]);
                a_src[j] += 512; b_src[j] += 256;
            }
            CPA_COMMIT();
        }
        tile_compute((const float*)(smem + (c % NSTAGE) * STAGE_B), mtb, ntb, lane, acc);
    }

    const int lr = lane >> 2, lc = lane & 3;
    const int rbase = base + m0 + (wid & 1) * 64 + lr;
    #pragma unroll
    for (int mt = 0; mt < 4; mt++) {
        int r = rbase + mt * 16;
        #pragma unroll
        for (int nt = 0; nt < 4; nt++) {
            int h = h0 + (wid >> 1) * 32 + nt * 8 + 2 * lc;
            *(float2*)(g_out2 + (size_t)r * H_DIM + h) =
                make_float2(acc[mt][nt][0], acc[mt][nt][1]);
            *(float2*)(g_out2 + (size_t)(r + 8) * H_DIM + h) =
                make_float2(acc[mt][nt][2], acc[mt][nt][3]);
        }
    }
}

// ---------------- combine ----------------
__global__ void combine_kernel(const float* __restrict__ w, float* __restrict__ out) {
    int t = blockIdx.x;
    float w0 = w[2 * t], w1 = w[2 * t + 1];
    const float4* a = (const float4*)(g_out2 + (size_t)g_pos[2 * t] * H_DIM);
    const float4* b = (const float4*)(g_out2 + (size_t)g_pos[2 * t + 1] * H_DIM);
    float4* o = (float4*)(out + (size_t)t * H_DIM);
    for (int j = threadIdx.x; j < H_DIM / 4; j += 256) {
        float4 va = a[j], vb = b[j], r;
        r.x = w0 * va.x + w1 * vb.x;
        r.y = w0 * va.y + w1 * vb.y;
        r.z = w0 * va.z + w1 * vb.z;
        r.w = w0 * va.w + w1 * vb.w;
        o[j] = r;
    }
}

// ---------------- launch (capture-forked streams) ----------------
static cudaStream_t s_w1, s_dw;
static cudaEvent_t  ev_root, ev_route, ev_w1, ev_dw;
static int s_init = 0;

extern "C" void kernel_launch(void* const* d_in, const int* in_sizes, int n_in,
                              void* d_out, int out_size) {
    const float* hidden = (const float*)d_in[0];
    const int*   topk_i = (const int*)d_in[1];
    const float* topk_w = (const float*)d_in[2];
    const float* gate_w = (const float*)d_in[3];
    const float* up_w   = (const float*)d_in[4];
    const float* down_w = (const float*)d_in[5];
    float* out = (float*)d_out;

    if (!s_init) {
        cudaStreamCreateWithFlags(&s_w1, cudaStreamNonBlocking);
        cudaStreamCreateWithFlags(&s_dw, cudaStreamNonBlocking);
        cudaEventCreateWithFlags(&ev_root,  cudaEventDisableTiming);
        cudaEventCreateWithFlags(&ev_route, cudaEventDisableTiming);
        cudaEventCreateWithFlags(&ev_w1,    cudaEventDisableTiming);
        cudaEventCreateWithFlags(&ev_dw,    cudaEventDisableTiming);
        cudaFuncSetAttribute(gemm1_kernel, cudaFuncAttributeMaxDynamicSharedMemorySize, SMEM_BYTES);
        cudaFuncSetAttribute(gemm2_kernel, cudaFuncAttributeMaxDynamicSharedMemorySize, SMEM_BYTES);
        s_init = 1;
    }

    // fork point: both weight-permute streams branch off the origin stream
    cudaEventRecord(ev_root, 0);
    cudaStreamWaitEvent(s_w1, ev_root, 0);
    cudaStreamWaitEvent(s_dw, ev_root, 0);

    // origin stream: routing + activation gather
    route_kernel<<<1, 256>>>(topk_i);
    gather_kernel<<<NROWS / 16, 256>>>(hidden);

    // forked: weight fragment permutes (independent of routing)
    permw1_kernel<<<E_NUM * 352, 256, 0, s_w1>>>(gate_w, up_w);
    cudaEventRecord(ev_w1, s_w1);
    permdw_kernel<<<E_NUM * 256, 256, 0, s_dw>>>(down_w);
    cudaEventRecord(ev_dw, s_dw);

    // GEMM1 needs gather (origin) + permw1; permdw keeps running underneath
    cudaStreamWaitEvent(0, ev_w1, 0);
    dim3 g1(I_DIM / 64, 64, E_NUM);
    gemm1_kernel<<<g1, 256, SMEM_BYTES>>>();

    // GEMM2 needs gemm1 (origin order) + permdw
    cudaStreamWaitEvent(0, ev_dw, 0);
    dim3 g2(H_DIM / 128, 64, E_NUM);
    gemm2_kernel<<<g2, 256, SMEM_BYTES>>>();

    combine_kernel<<<T_TOK, 256>>>(topk_w, out);
}